// round 2
// baseline (speedup 1.0000x reference)
#include <cuda_runtime.h>
#include <math.h>

#define S_LEN   8192
#define E_DIM   1024
#define H_DIM   2048
#define T_TAGS  50

// ---------------- persistent recurrence config ----------------
#define RB_NBLK    128
#define RB_ROWS    16          // H rows per block (128*16 = 2048)
#define RB_THREADS 256

// ---------------- scratch (static device memory; no allocs) ----------------
__device__ float g_xi[(size_t)S_LEN * H_DIM];    // 64 MB: xi = x@W_ih^T + b_ih + b_hh
__device__ float g_rnn[(size_t)S_LEN * H_DIM];   // 64 MB: all hidden states
__device__ volatile unsigned g_tag[RB_NBLK];     // per-block progress tags

__global__ void init_tags_kernel() {
    if (threadIdx.x < RB_NBLK) g_tag[threadIdx.x] = 0u;
}

// ---------------- Kernel 1: fused embedding gather + xi GEMM ----------------
// xi[s,h] = sum_e emb[sentence[s], e] * W_ih[h, e] + b_ih[h] + b_hh[h]
#define GBM 64
#define GBN 64
#define GBK 16

__global__ __launch_bounds__(256) void xi_gemm_kernel(
    const int*   __restrict__ sent,
    const float* __restrict__ emb,
    const float* __restrict__ W_ih,
    const float* __restrict__ b_ih,
    const float* __restrict__ b_hh)
{
    __shared__ float As[GBM][GBK + 1];   // [m][k], +1 pad to kill bank conflicts
    __shared__ float Bs[GBK][GBN + 4];   // [k][n], +4 pad keeps float4 alignment
    __shared__ int   sidx[GBM];

    const int tid = threadIdx.x;
    const int m0  = blockIdx.y * GBM;
    const int n0  = blockIdx.x * GBN;

    if (tid < GBM) sidx[tid] = sent[m0 + tid];
    __syncthreads();

    const int lr = tid >> 2;          // 0..63 : row within tile for loads
    const int lk = (tid & 3) * 4;     // 0,4,8,12 : k offset for float4 load

    const int tx = tid & 15;          // n direction (4 cols each)
    const int ty = tid >> 4;          // m direction (4 rows each)

    float acc[4][4];
#pragma unroll
    for (int i = 0; i < 4; i++)
#pragma unroll
        for (int j = 0; j < 4; j++) acc[i][j] = 0.f;

    const float* arow = emb  + (size_t)sidx[lr] * E_DIM;
    const float* brow = W_ih + (size_t)(n0 + lr) * E_DIM;

    for (int kt = 0; kt < E_DIM; kt += GBK) {
        float4 av = *(const float4*)(arow + kt + lk);
        float4 bv = *(const float4*)(brow + kt + lk);
        As[lr][lk + 0] = av.x; As[lr][lk + 1] = av.y;
        As[lr][lk + 2] = av.z; As[lr][lk + 3] = av.w;
        Bs[lk + 0][lr] = bv.x; Bs[lk + 1][lr] = bv.y;
        Bs[lk + 2][lr] = bv.z; Bs[lk + 3][lr] = bv.w;
        __syncthreads();

#pragma unroll
        for (int k = 0; k < GBK; k++) {
            float a0 = As[ty * 4 + 0][k];
            float a1 = As[ty * 4 + 1][k];
            float a2 = As[ty * 4 + 2][k];
            float a3 = As[ty * 4 + 3][k];
            float4 b4 = *(const float4*)&Bs[k][tx * 4];
            acc[0][0] = fmaf(a0, b4.x, acc[0][0]);
            acc[0][1] = fmaf(a0, b4.y, acc[0][1]);
            acc[0][2] = fmaf(a0, b4.z, acc[0][2]);
            acc[0][3] = fmaf(a0, b4.w, acc[0][3]);
            acc[1][0] = fmaf(a1, b4.x, acc[1][0]);
            acc[1][1] = fmaf(a1, b4.y, acc[1][1]);
            acc[1][2] = fmaf(a1, b4.z, acc[1][2]);
            acc[1][3] = fmaf(a1, b4.w, acc[1][3]);
            acc[2][0] = fmaf(a2, b4.x, acc[2][0]);
            acc[2][1] = fmaf(a2, b4.y, acc[2][1]);
            acc[2][2] = fmaf(a2, b4.z, acc[2][2]);
            acc[2][3] = fmaf(a2, b4.w, acc[2][3]);
            acc[3][0] = fmaf(a3, b4.x, acc[3][0]);
            acc[3][1] = fmaf(a3, b4.y, acc[3][1]);
            acc[3][2] = fmaf(a3, b4.z, acc[3][2]);
            acc[3][3] = fmaf(a3, b4.w, acc[3][3]);
        }
        __syncthreads();
    }

#pragma unroll
    for (int j = 0; j < 4; j++) {
        const int h = n0 + tx * 4 + j;
        const float bias = b_ih[h] + b_hh[h];
#pragma unroll
        for (int i = 0; i < 4; i++) {
            const int s = m0 + ty * 4 + i;
            g_xi[(size_t)s * H_DIM + h] = acc[i][j] + bias;
        }
    }
}

// ---------------- Kernel 2: persistent Elman recurrence ----------------
// h_t = tanh(xi_t + W_hh @ h_{t-1}), W_hh slice resident in SMEM.
// Cross-CTA sync: per-block monotonic tags in global memory.
__global__ void __launch_bounds__(RB_THREADS) rnn_kernel(
    const float* __restrict__ W_hh,
    const float* __restrict__ h0)
{
    extern __shared__ float smem[];
    float* sW = smem;                        // RB_ROWS * H_DIM floats
    float* sh = smem + RB_ROWS * H_DIM;      // H_DIM floats

    const int b   = blockIdx.x;
    const int tid = threadIdx.x;
    const int r0  = b * RB_ROWS;

    // load W_hh slice (128 KB) into SMEM once
    {
        const float4* wg  = (const float4*)(W_hh + (size_t)r0 * H_DIM);
        float4*       sW4 = (float4*)sW;
        for (int i = tid; i < RB_ROWS * H_DIM / 4; i += RB_THREADS) sW4[i] = wg[i];
        float4*       sh4 = (float4*)sh;
        const float4* h04 = (const float4*)h0;
        for (int i = tid; i < H_DIM / 4; i += RB_THREADS) sh4[i] = h04[i];
    }
    __syncthreads();

    const int warp = tid >> 5;
    const int lane = tid & 31;
    const int row0 = warp * 2;
    const int row1 = row0 + 1;
    const float* w0 = sW + (size_t)row0 * H_DIM;
    const float* w1 = sW + (size_t)row1 * H_DIM;
    const int gr0 = r0 + row0;
    const int gr1 = r0 + row1;

    float4* sh4 = (float4*)sh;

    for (int t = 0; t < S_LEN; t++) {
        // prefetch xi early to hide latency
        float xi0 = 0.f, xi1 = 0.f;
        if (lane == 0) {
            xi0 = g_xi[(size_t)t * H_DIM + gr0];
            xi1 = g_xi[(size_t)t * H_DIM + gr1];
        }

        float a0 = 0.f, a1 = 0.f;
#pragma unroll
        for (int k = 0; k < H_DIM; k += 128) {
            const int c = k + lane * 4;
            float4 hv = *(const float4*)(sh + c);
            float4 wa = *(const float4*)(w0 + c);
            float4 wb = *(const float4*)(w1 + c);
            a0 = fmaf(wa.x, hv.x, a0); a0 = fmaf(wa.y, hv.y, a0);
            a0 = fmaf(wa.z, hv.z, a0); a0 = fmaf(wa.w, hv.w, a0);
            a1 = fmaf(wb.x, hv.x, a1); a1 = fmaf(wb.y, hv.y, a1);
            a1 = fmaf(wb.z, hv.z, a1); a1 = fmaf(wb.w, hv.w, a1);
        }
#pragma unroll
        for (int off = 16; off; off >>= 1) {
            a0 += __shfl_down_sync(0xffffffffu, a0, off);
            a1 += __shfl_down_sync(0xffffffffu, a1, off);
        }

        if (lane == 0) {
            const float v0 = tanhf(xi0 + a0);
            const float v1 = tanhf(xi1 + a1);
            g_rnn[(size_t)t * H_DIM + gr0] = v0;
            g_rnn[(size_t)t * H_DIM + gr1] = v1;
            __threadfence();
        }
        // barrier covers: (a) all warps finished reading sh, (b) writers' stores fenced
        __syncthreads();
        if (tid == 0) g_tag[b] = (unsigned)(t + 1);

        if (t + 1 < S_LEN) {
            const unsigned want = (unsigned)(t + 1);
            if (tid < RB_NBLK) {
                while (g_tag[tid] < want) { /* spin on volatile */ }
            }
            __syncthreads();
            __threadfence();
            const float4* hr = (const float4*)(g_rnn + (size_t)t * H_DIM);
            for (int i = tid; i < H_DIM / 4; i += RB_THREADS) sh4[i] = hr[i];
            __syncthreads();
        }
    }
}

// ---------------- Kernel 3: tag head + log_softmax ----------------
#define OB_TOK     4
#define OB_THREADS 128

__global__ __launch_bounds__(OB_THREADS) void head_kernel(
    const float* __restrict__ W_out,
    const float* __restrict__ b_out,
    float*       __restrict__ out)
{
    __shared__ float shh[OB_TOK][H_DIM];
    __shared__ float ts[OB_TOK][T_TAGS];

    const int tid = threadIdx.x;
    const int s0  = blockIdx.x * OB_TOK;

    {
        const float4* src = (const float4*)(g_rnn + (size_t)s0 * H_DIM);
        float4*       dst = (float4*)&shh[0][0];
        for (int i = tid; i < OB_TOK * H_DIM / 4; i += OB_THREADS) dst[i] = src[i];
    }
    __syncthreads();

    if (tid < T_TAGS) {
        const float* w = W_out + (size_t)tid * H_DIM;
        float a0 = 0.f, a1 = 0.f, a2 = 0.f, a3 = 0.f;
        for (int c = 0; c < H_DIM; c += 4) {
            float4 w4 = *(const float4*)(w + c);
            float4 h0v = *(const float4*)&shh[0][c];
            float4 h1v = *(const float4*)&shh[1][c];
            float4 h2v = *(const float4*)&shh[2][c];
            float4 h3v = *(const float4*)&shh[3][c];
            a0 = fmaf(w4.x, h0v.x, a0); a0 = fmaf(w4.y, h0v.y, a0);
            a0 = fmaf(w4.z, h0v.z, a0); a0 = fmaf(w4.w, h0v.w, a0);
            a1 = fmaf(w4.x, h1v.x, a1); a1 = fmaf(w4.y, h1v.y, a1);
            a1 = fmaf(w4.z, h1v.z, a1); a1 = fmaf(w4.w, h1v.w, a1);
            a2 = fmaf(w4.x, h2v.x, a2); a2 = fmaf(w4.y, h2v.y, a2);
            a2 = fmaf(w4.z, h2v.z, a2); a2 = fmaf(w4.w, h2v.w, a2);
            a3 = fmaf(w4.x, h3v.x, a3); a3 = fmaf(w4.y, h3v.y, a3);
            a3 = fmaf(w4.z, h3v.z, a3); a3 = fmaf(w4.w, h3v.w, a3);
        }
        const float bo = b_out[tid];
        ts[0][tid] = a0 + bo;
        ts[1][tid] = a1 + bo;
        ts[2][tid] = a2 + bo;
        ts[3][tid] = a3 + bo;
    }
    __syncthreads();

    if (tid < OB_TOK) {
        float mx = -1e30f;
        for (int j = 0; j < T_TAGS; j++) mx = fmaxf(mx, ts[tid][j]);
        float sum = 0.f;
        for (int j = 0; j < T_TAGS; j++) sum += expf(ts[tid][j] - mx);
        const float lse = mx + logf(sum);
        float* o = out + (size_t)(s0 + tid) * T_TAGS;
        for (int j = 0; j < T_TAGS; j++) o[j] = ts[tid][j] - lse;
    }
}

// ---------------- launch ----------------
extern "C" void kernel_launch(void* const* d_in, const int* in_sizes, int n_in,
                              void* d_out, int out_size)
{
    const int*   sent  = (const int*)  d_in[0];
    const float* emb   = (const float*)d_in[1];
    const float* W_ih  = (const float*)d_in[2];
    const float* W_hh  = (const float*)d_in[3];
    const float* b_ih  = (const float*)d_in[4];
    const float* b_hh  = (const float*)d_in[5];
    const float* W_out = (const float*)d_in[6];
    const float* b_out = (const float*)d_in[7];
    const float* h0    = (const float*)d_in[8];
    float* out = (float*)d_out;

    (void)in_sizes; (void)n_in; (void)out_size;

    const size_t rsmem = (size_t)(RB_ROWS * H_DIM + H_DIM) * sizeof(float);
    cudaFuncSetAttribute(rnn_kernel, cudaFuncAttributeMaxDynamicSharedMemorySize,
                         (int)rsmem);

    init_tags_kernel<<<1, RB_NBLK>>>();

    dim3 ggrid(H_DIM / GBN, S_LEN / GBM);
    xi_gemm_kernel<<<ggrid, 256>>>(sent, emb, W_ih, b_ih, b_hh);

    rnn_kernel<<<RB_NBLK, RB_THREADS, rsmem>>>(W_hh, h0);

    head_kernel<<<S_LEN / OB_TOK, OB_THREADS>>>(W_out, b_out, out);
}

// round 3
// speedup vs baseline: 1.0178x; 1.0178x over previous
#include <cuda_runtime.h>
#include <math.h>

#define S_LEN   8192
#define E_DIM   1024
#define H_DIM   2048
#define T_TAGS  50

// ---------------- persistent recurrence config ----------------
#define RB_NBLK    128
#define RB_ROWS    16          // H rows per block (128*16 = 2048)
#define RB_THREADS 256

// ---------------- scratch (static device memory; no allocs) ----------------
__device__ float g_xi[(size_t)S_LEN * H_DIM];    // 64 MB: xi = x@W_ih^T + b_ih + b_hh
__device__ float g_rnn[(size_t)S_LEN * H_DIM];   // 64 MB: all hidden states
__device__ volatile unsigned g_tag[RB_NBLK];     // per-block progress tags

__global__ void init_tags_kernel() {
    if (threadIdx.x < RB_NBLK) g_tag[threadIdx.x] = 0u;
}

// ---------------- Kernel 1: fused embedding gather + xi GEMM ----------------
// xi[s,h] = sum_e emb[sentence[s], e] * W_ih[h, e] + b_ih[h] + b_hh[h]
#define GBM 64
#define GBN 64
#define GBK 16

__global__ __launch_bounds__(256) void xi_gemm_kernel(
    const int*   __restrict__ sent,
    const float* __restrict__ emb,
    const float* __restrict__ W_ih,
    const float* __restrict__ b_ih,
    const float* __restrict__ b_hh)
{
    __shared__ float As[GBM][GBK + 1];   // [m][k], +1 pad to kill bank conflicts
    __shared__ float Bs[GBK][GBN + 4];   // [k][n], +4 pad keeps float4 alignment
    __shared__ int   sidx[GBM];

    const int tid = threadIdx.x;
    const int m0  = blockIdx.y * GBM;
    const int n0  = blockIdx.x * GBN;

    if (tid < GBM) sidx[tid] = sent[m0 + tid];
    __syncthreads();

    const int lr = tid >> 2;          // 0..63 : row within tile for loads
    const int lk = (tid & 3) * 4;     // 0,4,8,12 : k offset for float4 load

    const int tx = tid & 15;          // n direction (4 cols each)
    const int ty = tid >> 4;          // m direction (4 rows each)

    float acc[4][4];
#pragma unroll
    for (int i = 0; i < 4; i++)
#pragma unroll
        for (int j = 0; j < 4; j++) acc[i][j] = 0.f;

    const float* arow = emb  + (size_t)sidx[lr] * E_DIM;
    const float* brow = W_ih + (size_t)(n0 + lr) * E_DIM;

    for (int kt = 0; kt < E_DIM; kt += GBK) {
        float4 av = *(const float4*)(arow + kt + lk);
        float4 bv = *(const float4*)(brow + kt + lk);
        As[lr][lk + 0] = av.x; As[lr][lk + 1] = av.y;
        As[lr][lk + 2] = av.z; As[lr][lk + 3] = av.w;
        Bs[lk + 0][lr] = bv.x; Bs[lk + 1][lr] = bv.y;
        Bs[lk + 2][lr] = bv.z; Bs[lk + 3][lr] = bv.w;
        __syncthreads();

#pragma unroll
        for (int k = 0; k < GBK; k++) {
            float a0 = As[ty * 4 + 0][k];
            float a1 = As[ty * 4 + 1][k];
            float a2 = As[ty * 4 + 2][k];
            float a3 = As[ty * 4 + 3][k];
            float4 b4 = *(const float4*)&Bs[k][tx * 4];
            acc[0][0] = fmaf(a0, b4.x, acc[0][0]);
            acc[0][1] = fmaf(a0, b4.y, acc[0][1]);
            acc[0][2] = fmaf(a0, b4.z, acc[0][2]);
            acc[0][3] = fmaf(a0, b4.w, acc[0][3]);
            acc[1][0] = fmaf(a1, b4.x, acc[1][0]);
            acc[1][1] = fmaf(a1, b4.y, acc[1][1]);
            acc[1][2] = fmaf(a1, b4.z, acc[1][2]);
            acc[1][3] = fmaf(a1, b4.w, acc[1][3]);
            acc[2][0] = fmaf(a2, b4.x, acc[2][0]);
            acc[2][1] = fmaf(a2, b4.y, acc[2][1]);
            acc[2][2] = fmaf(a2, b4.z, acc[2][2]);
            acc[2][3] = fmaf(a2, b4.w, acc[2][3]);
            acc[3][0] = fmaf(a3, b4.x, acc[3][0]);
            acc[3][1] = fmaf(a3, b4.y, acc[3][1]);
            acc[3][2] = fmaf(a3, b4.z, acc[3][2]);
            acc[3][3] = fmaf(a3, b4.w, acc[3][3]);
        }
        __syncthreads();
    }

#pragma unroll
    for (int j = 0; j < 4; j++) {
        const int h = n0 + tx * 4 + j;
        const float bias = b_ih[h] + b_hh[h];
#pragma unroll
        for (int i = 0; i < 4; i++) {
            const int s = m0 + ty * 4 + i;
            g_xi[(size_t)s * H_DIM + h] = acc[i][j] + bias;
        }
    }
}

// ---------------- Kernel 2: persistent Elman recurrence ----------------
// h_t = tanh(xi_t + W_hh @ h_{t-1}), W_hh slice resident in SMEM.
// Cross-CTA sync: per-block monotonic tags in global memory.
__global__ void __launch_bounds__(RB_THREADS) rnn_kernel(
    const float* __restrict__ W_hh,
    const float* __restrict__ h0)
{
    extern __shared__ float smem[];
    float* sW = smem;                        // RB_ROWS * H_DIM floats
    float* sh = smem + RB_ROWS * H_DIM;      // H_DIM floats

    const int b   = blockIdx.x;
    const int tid = threadIdx.x;
    const int r0  = b * RB_ROWS;

    // load W_hh slice (128 KB) into SMEM once
    {
        const float4* wg  = (const float4*)(W_hh + (size_t)r0 * H_DIM);
        float4*       sW4 = (float4*)sW;
        for (int i = tid; i < RB_ROWS * H_DIM / 4; i += RB_THREADS) sW4[i] = wg[i];
        float4*       sh4 = (float4*)sh;
        const float4* h04 = (const float4*)h0;
        for (int i = tid; i < H_DIM / 4; i += RB_THREADS) sh4[i] = h04[i];
    }
    __syncthreads();

    const int warp = tid >> 5;
    const int lane = tid & 31;
    const int row0 = warp * 2;
    const int row1 = row0 + 1;
    const float* w0 = sW + (size_t)row0 * H_DIM;
    const float* w1 = sW + (size_t)row1 * H_DIM;
    const int gr0 = r0 + row0;
    const int gr1 = r0 + row1;

    float4* sh4 = (float4*)sh;

    for (int t = 0; t < S_LEN; t++) {
        // prefetch xi early to hide latency
        float xi0 = 0.f, xi1 = 0.f;
        if (lane == 0) {
            xi0 = g_xi[(size_t)t * H_DIM + gr0];
            xi1 = g_xi[(size_t)t * H_DIM + gr1];
        }

        float a0 = 0.f, a1 = 0.f;
#pragma unroll
        for (int k = 0; k < H_DIM; k += 128) {
            const int c = k + lane * 4;
            float4 hv = *(const float4*)(sh + c);
            float4 wa = *(const float4*)(w0 + c);
            float4 wb = *(const float4*)(w1 + c);
            a0 = fmaf(wa.x, hv.x, a0); a0 = fmaf(wa.y, hv.y, a0);
            a0 = fmaf(wa.z, hv.z, a0); a0 = fmaf(wa.w, hv.w, a0);
            a1 = fmaf(wb.x, hv.x, a1); a1 = fmaf(wb.y, hv.y, a1);
            a1 = fmaf(wb.z, hv.z, a1); a1 = fmaf(wb.w, hv.w, a1);
        }
#pragma unroll
        for (int off = 16; off; off >>= 1) {
            a0 += __shfl_down_sync(0xffffffffu, a0, off);
            a1 += __shfl_down_sync(0xffffffffu, a1, off);
        }

        if (lane == 0) {
            const float v0 = tanhf(xi0 + a0);
            const float v1 = tanhf(xi1 + a1);
            g_rnn[(size_t)t * H_DIM + gr0] = v0;
            g_rnn[(size_t)t * H_DIM + gr1] = v1;
            __threadfence();
        }
        // barrier covers: (a) all warps finished reading sh, (b) writers' stores fenced
        __syncthreads();
        if (tid == 0) g_tag[b] = (unsigned)(t + 1);

        if (t + 1 < S_LEN) {
            const unsigned want = (unsigned)(t + 1);
            if (tid < RB_NBLK) {
                while (g_tag[tid] < want) { /* spin on volatile */ }
            }
            __syncthreads();
            __threadfence();
            const float4* hr = (const float4*)(g_rnn + (size_t)t * H_DIM);
            for (int i = tid; i < H_DIM / 4; i += RB_THREADS) sh4[i] = hr[i];
            __syncthreads();
        }
    }
}

// ---------------- Kernel 3: tag head + log_softmax ----------------
#define OB_TOK     4
#define OB_THREADS 128

__global__ __launch_bounds__(OB_THREADS) void head_kernel(
    const float* __restrict__ W_out,
    const float* __restrict__ b_out,
    float*       __restrict__ out)
{
    __shared__ float shh[OB_TOK][H_DIM];
    __shared__ float ts[OB_TOK][T_TAGS];

    const int tid = threadIdx.x;
    const int s0  = blockIdx.x * OB_TOK;

    {
        const float4* src = (const float4*)(g_rnn + (size_t)s0 * H_DIM);
        float4*       dst = (float4*)&shh[0][0];
        for (int i = tid; i < OB_TOK * H_DIM / 4; i += OB_THREADS) dst[i] = src[i];
    }
    __syncthreads();

    if (tid < T_TAGS) {
        const float* w = W_out + (size_t)tid * H_DIM;
        float a0 = 0.f, a1 = 0.f, a2 = 0.f, a3 = 0.f;
        for (int c = 0; c < H_DIM; c += 4) {
            float4 w4 = *(const float4*)(w + c);
            float4 h0v = *(const float4*)&shh[0][c];
            float4 h1v = *(const float4*)&shh[1][c];
            float4 h2v = *(const float4*)&shh[2][c];
            float4 h3v = *(const float4*)&shh[3][c];
            a0 = fmaf(w4.x, h0v.x, a0); a0 = fmaf(w4.y, h0v.y, a0);
            a0 = fmaf(w4.z, h0v.z, a0); a0 = fmaf(w4.w, h0v.w, a0);
            a1 = fmaf(w4.x, h1v.x, a1); a1 = fmaf(w4.y, h1v.y, a1);
            a1 = fmaf(w4.z, h1v.z, a1); a1 = fmaf(w4.w, h1v.w, a1);
            a2 = fmaf(w4.x, h2v.x, a2); a2 = fmaf(w4.y, h2v.y, a2);
            a2 = fmaf(w4.z, h2v.z, a2); a2 = fmaf(w4.w, h2v.w, a2);
            a3 = fmaf(w4.x, h3v.x, a3); a3 = fmaf(w4.y, h3v.y, a3);
            a3 = fmaf(w4.z, h3v.z, a3); a3 = fmaf(w4.w, h3v.w, a3);
        }
        const float bo = b_out[tid];
        ts[0][tid] = a0 + bo;
        ts[1][tid] = a1 + bo;
        ts[2][tid] = a2 + bo;
        ts[3][tid] = a3 + bo;
    }
    __syncthreads();

    if (tid < OB_TOK) {
        float mx = -1e30f;
        for (int j = 0; j < T_TAGS; j++) mx = fmaxf(mx, ts[tid][j]);
        float sum = 0.f;
        for (int j = 0; j < T_TAGS; j++) sum += expf(ts[tid][j] - mx);
        const float lse = mx + logf(sum);
        float* o = out + (size_t)(s0 + tid) * T_TAGS;
        for (int j = 0; j < T_TAGS; j++) o[j] = ts[tid][j] - lse;
    }
}

// ---------------- launch ----------------
extern "C" void kernel_launch(void* const* d_in, const int* in_sizes, int n_in,
                              void* d_out, int out_size)
{
    const int*   sent  = (const int*)  d_in[0];
    const float* emb   = (const float*)d_in[1];
    const float* W_ih  = (const float*)d_in[2];
    const float* W_hh  = (const float*)d_in[3];
    const float* b_ih  = (const float*)d_in[4];
    const float* b_hh  = (const float*)d_in[5];
    const float* W_out = (const float*)d_in[6];
    const float* b_out = (const float*)d_in[7];
    const float* h0    = (const float*)d_in[8];
    float* out = (float*)d_out;

    (void)in_sizes; (void)n_in; (void)out_size;

    const size_t rsmem = (size_t)(RB_ROWS * H_DIM + H_DIM) * sizeof(float);
    cudaFuncSetAttribute(rnn_kernel, cudaFuncAttributeMaxDynamicSharedMemorySize,
                         (int)rsmem);

    init_tags_kernel<<<1, RB_NBLK>>>();

    dim3 ggrid(H_DIM / GBN, S_LEN / GBM);
    xi_gemm_kernel<<<ggrid, 256>>>(sent, emb, W_ih, b_ih, b_hh);

    rnn_kernel<<<RB_NBLK, RB_THREADS, rsmem>>>(W_hh, h0);

    head_kernel<<<S_LEN / OB_TOK, OB_THREADS>>>(W_out, b_out, out);
}

// round 5
// speedup vs baseline: 4.1186x; 4.0465x over previous
#include <cuda_runtime.h>
#include <math.h>
#include <stdint.h>

#define S_LEN   8192
#define E_DIM   1024
#define H_DIM   2048
#define T_TAGS  50

// ---------------- persistent recurrence config ----------------
#define RB_NBLK    128
#define RB_ROWS    16          // H rows per block (128*16 = 2048)
#define RB_THREADS 256         // 8 warps * 2 rows = 16 rows

// ---------------- scratch (static device memory; no allocs) ----------------
__device__ float g_xi[(size_t)S_LEN * H_DIM];    // 64 MB: xi = x@W_ih^T + b_ih + b_hh
__device__ float g_rnn[(size_t)S_LEN * H_DIM];   // 64 MB: all hidden states
__device__ unsigned g_cnt;                       // grid-barrier epoch counter

__global__ void init_cnt_kernel() {
    if (threadIdx.x == 0) g_cnt = 0u;
}

// ---------------- packed f32x2 helpers ----------------
__device__ __forceinline__ unsigned long long ffma2(unsigned long long a,
                                                    unsigned long long b,
                                                    unsigned long long c) {
    unsigned long long d;
    asm("fma.rn.f32x2 %0, %1, %2, %3;" : "=l"(d) : "l"(a), "l"(b), "l"(c));
    return d;
}

// ---------------- Kernel 1: fused embedding gather + xi GEMM ----------------
#define GBM 64
#define GBN 64
#define GBK 16

__global__ __launch_bounds__(256) void xi_gemm_kernel(
    const int*   __restrict__ sent,
    const float* __restrict__ emb,
    const float* __restrict__ W_ih,
    const float* __restrict__ b_ih,
    const float* __restrict__ b_hh)
{
    __shared__ float As[GBM][GBK + 1];
    __shared__ float Bs[GBK][GBN + 4];
    __shared__ int   sidx[GBM];

    const int tid = threadIdx.x;
    const int m0  = blockIdx.y * GBM;
    const int n0  = blockIdx.x * GBN;

    if (tid < GBM) sidx[tid] = sent[m0 + tid];
    __syncthreads();

    const int lr = tid >> 2;
    const int lk = (tid & 3) * 4;

    const int tx = tid & 15;
    const int ty = tid >> 4;

    float acc[4][4];
#pragma unroll
    for (int i = 0; i < 4; i++)
#pragma unroll
        for (int j = 0; j < 4; j++) acc[i][j] = 0.f;

    const float* arow = emb  + (size_t)sidx[lr] * E_DIM;
    const float* brow = W_ih + (size_t)(n0 + lr) * E_DIM;

    for (int kt = 0; kt < E_DIM; kt += GBK) {
        float4 av = *(const float4*)(arow + kt + lk);
        float4 bv = *(const float4*)(brow + kt + lk);
        As[lr][lk + 0] = av.x; As[lr][lk + 1] = av.y;
        As[lr][lk + 2] = av.z; As[lr][lk + 3] = av.w;
        Bs[lk + 0][lr] = bv.x; Bs[lk + 1][lr] = bv.y;
        Bs[lk + 2][lr] = bv.z; Bs[lk + 3][lr] = bv.w;
        __syncthreads();

#pragma unroll
        for (int k = 0; k < GBK; k++) {
            float a0 = As[ty * 4 + 0][k];
            float a1 = As[ty * 4 + 1][k];
            float a2 = As[ty * 4 + 2][k];
            float a3 = As[ty * 4 + 3][k];
            float4 b4 = *(const float4*)&Bs[k][tx * 4];
            acc[0][0] = fmaf(a0, b4.x, acc[0][0]);
            acc[0][1] = fmaf(a0, b4.y, acc[0][1]);
            acc[0][2] = fmaf(a0, b4.z, acc[0][2]);
            acc[0][3] = fmaf(a0, b4.w, acc[0][3]);
            acc[1][0] = fmaf(a1, b4.x, acc[1][0]);
            acc[1][1] = fmaf(a1, b4.y, acc[1][1]);
            acc[1][2] = fmaf(a1, b4.z, acc[1][2]);
            acc[1][3] = fmaf(a1, b4.w, acc[1][3]);
            acc[2][0] = fmaf(a2, b4.x, acc[2][0]);
            acc[2][1] = fmaf(a2, b4.y, acc[2][1]);
            acc[2][2] = fmaf(a2, b4.z, acc[2][2]);
            acc[2][3] = fmaf(a2, b4.w, acc[2][3]);
            acc[3][0] = fmaf(a3, b4.x, acc[3][0]);
            acc[3][1] = fmaf(a3, b4.y, acc[3][1]);
            acc[3][2] = fmaf(a3, b4.z, acc[3][2]);
            acc[3][3] = fmaf(a3, b4.w, acc[3][3]);
        }
        __syncthreads();
    }

#pragma unroll
    for (int j = 0; j < 4; j++) {
        const int h = n0 + tx * 4 + j;
        const float bias = b_ih[h] + b_hh[h];
#pragma unroll
        for (int i = 0; i < 4; i++) {
            const int s = m0 + ty * 4 + i;
            g_xi[(size_t)s * H_DIM + h] = acc[i][j] + bias;
        }
    }
}

// ---------------- Kernel 2: persistent Elman recurrence ----------------
// W_hh rows live in REGISTERS (2 rows/warp, 64 f32x2 regs/lane).
// h_{t-1} staged into SMEM once per step; grid barrier = single release/acquire
// epoch counter (cooperative-groups pattern, tid0 only).
// NOTE: the SMEM loads in the matvec MUST be asm volatile + "memory" clobber:
// their address is loop-invariant, and a non-volatile asm gets CSE'd out of
// the t-loop (the R4 bug: h frozen at h0 -> rel_err 6e-3).
__global__ void __launch_bounds__(RB_THREADS, 1) rnn_kernel(
    const float* __restrict__ W_hh,
    const float* __restrict__ h0)
{
    __shared__ float sh[H_DIM];   // 8 KB: previous hidden state

    const int b    = blockIdx.x;
    const int tid  = threadIdx.x;
    const int warp = tid >> 5;
    const int lane = tid & 31;

    const int gr0 = b * RB_ROWS + warp * 2;   // even
    const int gr1 = gr0 + 1;

    // ---- load 2 W_hh rows into registers (packed f32x2) ----
    unsigned long long w0p[32], w1p[32];
    {
        const float* wr0 = W_hh + (size_t)gr0 * H_DIM + lane * 4;
        const float* wr1 = W_hh + (size_t)gr1 * H_DIM + lane * 4;
#pragma unroll
        for (int c = 0; c < 16; c++) {
            ulonglong2 v0 = *(const ulonglong2*)(wr0 + c * 128);
            ulonglong2 v1 = *(const ulonglong2*)(wr1 + c * 128);
            w0p[2 * c] = v0.x; w0p[2 * c + 1] = v0.y;
            w1p[2 * c] = v1.x; w1p[2 * c + 1] = v1.y;
        }
    }

    // ---- stage h0 ----
    {
        const float4* src = (const float4*)h0;
        float4*       dst = (float4*)sh;
#pragma unroll
        for (int i = 0; i < H_DIM / 4 / RB_THREADS; i++)
            dst[tid + i * RB_THREADS] = src[tid + i * RB_THREADS];
    }
    __syncthreads();

    const uint32_t sh_base =
        (uint32_t)__cvta_generic_to_shared(sh) + (uint32_t)(lane * 16);

    for (int t = 0; t < S_LEN; t++) {
        // prefetch xi (needed only after the matvec)
        float xi0 = 0.f, xi1 = 0.f;
        if (lane == 0) {
            const float2 xv = *(const float2*)(g_xi + (size_t)t * H_DIM + gr0);
            xi0 = xv.x; xi1 = xv.y;
        }

        // ---- matvec: 2 rows x 2048, W in regs, h from SMEM ----
        unsigned long long acc0 = 0ull, acc1 = 0ull;
#pragma unroll
        for (int c = 0; c < 16; c++) {
            unsigned long long h01, h23;
            asm volatile("ld.shared.v2.b64 {%0, %1}, [%2];"
                         : "=l"(h01), "=l"(h23)
                         : "r"(sh_base + (uint32_t)(c * 512))
                         : "memory");
            acc0 = ffma2(w0p[2 * c],     h01, acc0);
            acc0 = ffma2(w0p[2 * c + 1], h23, acc0);
            acc1 = ffma2(w1p[2 * c],     h01, acc1);
            acc1 = ffma2(w1p[2 * c + 1], h23, acc1);
        }

        float a0, a1;
        {
            float lo, hi;
            asm("mov.b64 {%0, %1}, %2;" : "=f"(lo), "=f"(hi) : "l"(acc0));
            a0 = lo + hi;
            asm("mov.b64 {%0, %1}, %2;" : "=f"(lo), "=f"(hi) : "l"(acc1));
            a1 = lo + hi;
        }
#pragma unroll
        for (int off = 16; off; off >>= 1) {
            a0 += __shfl_down_sync(0xffffffffu, a0, off);
            a1 += __shfl_down_sync(0xffffffffu, a1, off);
        }

        if (lane == 0) {
            float2 hv;
            hv.x = tanhf(xi0 + a0);
            hv.y = tanhf(xi1 + a1);
            __stcg((float2*)(g_rnn + (size_t)t * H_DIM + gr0), hv);
        }

        __syncthreads();   // all warps done reading sh; all h stores issued

        if (tid == 0) {
            asm volatile("red.release.gpu.global.add.u32 [%0], %1;"
                         :: "l"(&g_cnt), "r"(1u) : "memory");
        }

        if (t + 1 < S_LEN) {
            if (tid == 0) {
                const unsigned want = (unsigned)(RB_NBLK * (t + 1));
                unsigned v;
                do {
                    asm volatile("ld.acquire.gpu.global.u32 %0, [%1];"
                                 : "=r"(v) : "l"(&g_cnt) : "memory");
                } while (v < want);
            }
            __syncthreads();

            // stage h_t (L1-bypass: written by other SMs this launch)
            const float4* src = (const float4*)(g_rnn + (size_t)t * H_DIM);
            float4*       dst = (float4*)sh;
#pragma unroll
            for (int i = 0; i < H_DIM / 4 / RB_THREADS; i++)
                dst[tid + i * RB_THREADS] = __ldcg(src + tid + i * RB_THREADS);
            __syncthreads();
        }
    }
}

// ---------------- Kernel 3: tag head + log_softmax ----------------
#define OB_TOK     4
#define OB_THREADS 128

__global__ __launch_bounds__(OB_THREADS) void head_kernel(
    const float* __restrict__ W_out,
    const float* __restrict__ b_out,
    float*       __restrict__ out)
{
    __shared__ float shh[OB_TOK][H_DIM];
    __shared__ float ts[OB_TOK][T_TAGS];

    const int tid = threadIdx.x;
    const int s0  = blockIdx.x * OB_TOK;

    {
        const float4* src = (const float4*)(g_rnn + (size_t)s0 * H_DIM);
        float4*       dst = (float4*)&shh[0][0];
        for (int i = tid; i < OB_TOK * H_DIM / 4; i += OB_THREADS) dst[i] = src[i];
    }
    __syncthreads();

    if (tid < T_TAGS) {
        const float* w = W_out + (size_t)tid * H_DIM;
        float a0 = 0.f, a1 = 0.f, a2 = 0.f, a3 = 0.f;
        for (int c = 0; c < H_DIM; c += 4) {
            float4 w4 = *(const float4*)(w + c);
            float4 h0v = *(const float4*)&shh[0][c];
            float4 h1v = *(const float4*)&shh[1][c];
            float4 h2v = *(const float4*)&shh[2][c];
            float4 h3v = *(const float4*)&shh[3][c];
            a0 = fmaf(w4.x, h0v.x, a0); a0 = fmaf(w4.y, h0v.y, a0);
            a0 = fmaf(w4.z, h0v.z, a0); a0 = fmaf(w4.w, h0v.w, a0);
            a1 = fmaf(w4.x, h1v.x, a1); a1 = fmaf(w4.y, h1v.y, a1);
            a1 = fmaf(w4.z, h1v.z, a1); a1 = fmaf(w4.w, h1v.w, a1);
            a2 = fmaf(w4.x, h2v.x, a2); a2 = fmaf(w4.y, h2v.y, a2);
            a2 = fmaf(w4.z, h2v.z, a2); a2 = fmaf(w4.w, h2v.w, a2);
            a3 = fmaf(w4.x, h3v.x, a3); a3 = fmaf(w4.y, h3v.y, a3);
            a3 = fmaf(w4.z, h3v.z, a3); a3 = fmaf(w4.w, h3v.w, a3);
        }
        const float bo = b_out[tid];
        ts[0][tid] = a0 + bo;
        ts[1][tid] = a1 + bo;
        ts[2][tid] = a2 + bo;
        ts[3][tid] = a3 + bo;
    }
    __syncthreads();

    if (tid < OB_TOK) {
        float mx = -1e30f;
        for (int j = 0; j < T_TAGS; j++) mx = fmaxf(mx, ts[tid][j]);
        float sum = 0.f;
        for (int j = 0; j < T_TAGS; j++) sum += expf(ts[tid][j] - mx);
        const float lse = mx + logf(sum);
        float* o = out + (size_t)(s0 + tid) * T_TAGS;
        for (int j = 0; j < T_TAGS; j++) o[j] = ts[tid][j] - lse;
    }
}

// ---------------- launch ----------------
extern "C" void kernel_launch(void* const* d_in, const int* in_sizes, int n_in,
                              void* d_out, int out_size)
{
    const int*   sent  = (const int*)  d_in[0];
    const float* emb   = (const float*)d_in[1];
    const float* W_ih  = (const float*)d_in[2];
    const float* W_hh  = (const float*)d_in[3];
    const float* b_ih  = (const float*)d_in[4];
    const float* b_hh  = (const float*)d_in[5];
    const float* W_out = (const float*)d_in[6];
    const float* b_out = (const float*)d_in[7];
    const float* h0    = (const float*)d_in[8];
    float* out = (float*)d_out;

    (void)in_sizes; (void)n_in; (void)out_size;

    init_cnt_kernel<<<1, 32>>>();

    dim3 ggrid(H_DIM / GBN, S_LEN / GBM);
    xi_gemm_kernel<<<ggrid, 256>>>(sent, emb, W_ih, b_ih, b_hh);

    rnn_kernel<<<RB_NBLK, RB_THREADS>>>(W_hh, h0);

    head_kernel<<<S_LEN / OB_TOK, OB_THREADS>>>(W_out, b_out, out);
}

// round 6
// speedup vs baseline: 4.2031x; 1.0205x over previous
#include <cuda_runtime.h>
#include <math.h>
#include <stdint.h>

#define S_LEN   8192
#define E_DIM   1024
#define H_DIM   2048
#define T_TAGS  50

// ---------------- persistent recurrence config ----------------
#define RB_NBLK    128
#define RB_ROWS    16          // H rows per block (128*16 = 2048)
#define RB_THREADS 256         // 8 warps * 2 rows = 16 rows
#define N_GRP      8           // counter/chunk groups (16 CTAs, 256 rows each)
#define GRP_CTAS   (RB_NBLK / N_GRP)    // 16
#define CHUNK      (H_DIM / N_GRP)      // 256 floats per chunk

// ---------------- scratch (static device memory; no allocs) ----------------
__device__ float g_xi[(size_t)S_LEN * H_DIM];    // 64 MB
__device__ float g_rnn[(size_t)S_LEN * H_DIM];   // 64 MB
__device__ unsigned g_cnt8[N_GRP * 32];          // 8 counters, 128B apart

__global__ void init_cnt_kernel() {
    if (threadIdx.x < N_GRP * 32) g_cnt8[threadIdx.x] = 0u;
}

// ---------------- packed f32x2 helpers ----------------
__device__ __forceinline__ unsigned long long ffma2(unsigned long long a,
                                                    unsigned long long b,
                                                    unsigned long long c) {
    unsigned long long d;
    asm("fma.rn.f32x2 %0, %1, %2, %3;" : "=l"(d) : "l"(a), "l"(b), "l"(c));
    return d;
}

// ---------------- Kernel 1: fused embedding gather + xi GEMM ----------------
#define GBM 64
#define GBN 64
#define GBK 16

__global__ __launch_bounds__(256) void xi_gemm_kernel(
    const int*   __restrict__ sent,
    const float* __restrict__ emb,
    const float* __restrict__ W_ih,
    const float* __restrict__ b_ih,
    const float* __restrict__ b_hh)
{
    __shared__ float As[GBM][GBK + 1];
    __shared__ float Bs[GBK][GBN + 4];
    __shared__ int   sidx[GBM];

    const int tid = threadIdx.x;
    const int m0  = blockIdx.y * GBM;
    const int n0  = blockIdx.x * GBN;

    if (tid < GBM) sidx[tid] = sent[m0 + tid];
    __syncthreads();

    const int lr = tid >> 2;
    const int lk = (tid & 3) * 4;

    const int tx = tid & 15;
    const int ty = tid >> 4;

    float acc[4][4];
#pragma unroll
    for (int i = 0; i < 4; i++)
#pragma unroll
        for (int j = 0; j < 4; j++) acc[i][j] = 0.f;

    const float* arow = emb  + (size_t)sidx[lr] * E_DIM;
    const float* brow = W_ih + (size_t)(n0 + lr) * E_DIM;

    for (int kt = 0; kt < E_DIM; kt += GBK) {
        float4 av = *(const float4*)(arow + kt + lk);
        float4 bv = *(const float4*)(brow + kt + lk);
        As[lr][lk + 0] = av.x; As[lr][lk + 1] = av.y;
        As[lr][lk + 2] = av.z; As[lr][lk + 3] = av.w;
        Bs[lk + 0][lr] = bv.x; Bs[lk + 1][lr] = bv.y;
        Bs[lk + 2][lr] = bv.z; Bs[lk + 3][lr] = bv.w;
        __syncthreads();

#pragma unroll
        for (int k = 0; k < GBK; k++) {
            float a0 = As[ty * 4 + 0][k];
            float a1 = As[ty * 4 + 1][k];
            float a2 = As[ty * 4 + 2][k];
            float a3 = As[ty * 4 + 3][k];
            float4 b4 = *(const float4*)&Bs[k][tx * 4];
            acc[0][0] = fmaf(a0, b4.x, acc[0][0]);
            acc[0][1] = fmaf(a0, b4.y, acc[0][1]);
            acc[0][2] = fmaf(a0, b4.z, acc[0][2]);
            acc[0][3] = fmaf(a0, b4.w, acc[0][3]);
            acc[1][0] = fmaf(a1, b4.x, acc[1][0]);
            acc[1][1] = fmaf(a1, b4.y, acc[1][1]);
            acc[1][2] = fmaf(a1, b4.z, acc[1][2]);
            acc[1][3] = fmaf(a1, b4.w, acc[1][3]);
            acc[2][0] = fmaf(a2, b4.x, acc[2][0]);
            acc[2][1] = fmaf(a2, b4.y, acc[2][1]);
            acc[2][2] = fmaf(a2, b4.z, acc[2][2]);
            acc[2][3] = fmaf(a2, b4.w, acc[2][3]);
            acc[3][0] = fmaf(a3, b4.x, acc[3][0]);
            acc[3][1] = fmaf(a3, b4.y, acc[3][1]);
            acc[3][2] = fmaf(a3, b4.z, acc[3][2]);
            acc[3][3] = fmaf(a3, b4.w, acc[3][3]);
        }
        __syncthreads();
    }

#pragma unroll
    for (int j = 0; j < 4; j++) {
        const int h = n0 + tx * 4 + j;
        const float bias = b_ih[h] + b_hh[h];
#pragma unroll
        for (int i = 0; i < 4; i++) {
            const int s = m0 + ty * 4 + i;
            g_xi[(size_t)s * H_DIM + h] = acc[i][j] + bias;
        }
    }
}

// ---------------- Kernel 2: persistent Elman recurrence ----------------
// W_hh rows in registers (2 rows/warp, f32x2). Sync: 8 chunk counters;
// CTA b arrives on counter[b/16]; warp w of every CTA polls counter[w]
// (acquire) and stages h-chunk w — point-to-point, no full grid barrier.
// SMEM matvec loads are asm volatile + "memory" (R4 lesson: loop-invariant
// address gets CSE'd otherwise).
__global__ void __launch_bounds__(RB_THREADS, 1) rnn_kernel(
    const float* __restrict__ W_hh,
    const float* __restrict__ h0)
{
    __shared__ float sh[H_DIM];   // 8 KB: previous hidden state

    const int b    = blockIdx.x;
    const int tid  = threadIdx.x;
    const int warp = tid >> 5;
    const int lane = tid & 31;

    const int gr0 = b * RB_ROWS + warp * 2;
    const int gr1 = gr0 + 1;

    // ---- load 2 W_hh rows into registers (packed f32x2) ----
    unsigned long long w0p[32], w1p[32];
    {
        const float* wr0 = W_hh + (size_t)gr0 * H_DIM + lane * 4;
        const float* wr1 = W_hh + (size_t)gr1 * H_DIM + lane * 4;
#pragma unroll
        for (int c = 0; c < 16; c++) {
            ulonglong2 v0 = *(const ulonglong2*)(wr0 + c * 128);
            ulonglong2 v1 = *(const ulonglong2*)(wr1 + c * 128);
            w0p[2 * c] = v0.x; w0p[2 * c + 1] = v0.y;
            w1p[2 * c] = v1.x; w1p[2 * c + 1] = v1.y;
        }
    }

    // ---- stage h0 ----
    {
        const float4* src = (const float4*)h0;
        float4*       dst = (float4*)sh;
#pragma unroll
        for (int i = 0; i < H_DIM / 4 / RB_THREADS; i++)
            dst[tid + i * RB_THREADS] = src[tid + i * RB_THREADS];
    }
    __syncthreads();

    const uint32_t sh_base =
        (uint32_t)__cvta_generic_to_shared(sh) + (uint32_t)(lane * 16);

    unsigned* my_cnt   = &g_cnt8[(b >> 4) * 32];   // arrival counter
    unsigned* poll_cnt = &g_cnt8[warp * 32];       // chunk this warp stages

    // staging addresses for chunk `warp`: lane loads 8 floats (2 float4)
    const int chunk_off = warp * CHUNK + lane * 8;
    float4* sh_st = (float4*)(sh + chunk_off);

    for (int t = 0; t < S_LEN; t++) {
        float xi0 = 0.f, xi1 = 0.f;
        if (lane == 0) {
            const float2 xv = *(const float2*)(g_xi + (size_t)t * H_DIM + gr0);
            xi0 = xv.x; xi1 = xv.y;
        }

        // ---- matvec: 2 rows x 2048, W in regs, h from SMEM ----
        unsigned long long acc0 = 0ull, acc1 = 0ull;
#pragma unroll
        for (int c = 0; c < 16; c++) {
            unsigned long long h01, h23;
            asm volatile("ld.shared.v2.b64 {%0, %1}, [%2];"
                         : "=l"(h01), "=l"(h23)
                         : "r"(sh_base + (uint32_t)(c * 512))
                         : "memory");
            acc0 = ffma2(w0p[2 * c],     h01, acc0);
            acc0 = ffma2(w0p[2 * c + 1], h23, acc0);
            acc1 = ffma2(w1p[2 * c],     h01, acc1);
            acc1 = ffma2(w1p[2 * c + 1], h23, acc1);
        }

        float a0, a1;
        {
            float lo, hi;
            asm("mov.b64 {%0, %1}, %2;" : "=f"(lo), "=f"(hi) : "l"(acc0));
            a0 = lo + hi;
            asm("mov.b64 {%0, %1}, %2;" : "=f"(lo), "=f"(hi) : "l"(acc1));
            a1 = lo + hi;
        }
#pragma unroll
        for (int off = 16; off; off >>= 1) {
            a0 += __shfl_down_sync(0xffffffffu, a0, off);
            a1 += __shfl_down_sync(0xffffffffu, a1, off);
        }

        if (lane == 0) {
            float2 hv;
            hv.x = tanhf(xi0 + a0);
            hv.y = tanhf(xi1 + a1);
            __stcg((float2*)(g_rnn + (size_t)t * H_DIM + gr0), hv);
        }

        // bar: (a) all warps done reading sh (safe to restage),
        //      (b) all h stores happen-before tid0's release (cumulativity)
        __syncthreads();

        if (tid == 0) {
            asm volatile("red.release.gpu.global.add.u32 [%0], %1;"
                         :: "l"(my_cnt), "r"(1u) : "memory");
        }

        if (t + 1 < S_LEN) {
            // warp w waits for the 16 producers of chunk w (point-to-point)
            const unsigned want = (unsigned)(GRP_CTAS * (t + 1));
            unsigned v;
            do {
                asm volatile("ld.acquire.gpu.global.u32 %0, [%1];"
                             : "=r"(v) : "l"(poll_cnt) : "memory");
            } while (v < want);

            // stage chunk w (L1-bypass: written by other SMs)
            const float4* src =
                (const float4*)(g_rnn + (size_t)t * H_DIM + chunk_off);
            sh_st[0] = __ldcg(src + 0);
            sh_st[1] = __ldcg(src + 1);
            __syncthreads();   // all chunks staged before next matvec
        }
    }
}

// ---------------- Kernel 3: tag head + log_softmax ----------------
#define OB_TOK     4
#define OB_THREADS 256

__global__ __launch_bounds__(OB_THREADS) void head_kernel(
    const float* __restrict__ W_out,
    const float* __restrict__ b_out,
    float*       __restrict__ out)
{
    __shared__ float shh[OB_TOK][H_DIM];
    __shared__ float ts[OB_TOK][64];

    const int tid = threadIdx.x;
    const int s0  = blockIdx.x * OB_TOK;

    {
        const float4* src = (const float4*)(g_rnn + (size_t)s0 * H_DIM);
        float4*       dst = (float4*)&shh[0][0];
        for (int i = tid; i < OB_TOK * H_DIM / 4; i += OB_THREADS) dst[i] = src[i];
    }
    __syncthreads();

    // one (token, tag) dot per thread: tag = tid&63, tok = tid>>6
    {
        const int j   = tid & 63;
        const int tok = tid >> 6;
        if (j < T_TAGS) {
            const float* w = W_out + (size_t)j * H_DIM;
            const float* h = &shh[tok][0];
            float acc = 0.f;
            for (int c = 0; c < H_DIM; c += 4) {
                float4 w4 = *(const float4*)(w + c);
                float4 h4 = *(const float4*)(h + c);
                acc = fmaf(w4.x, h4.x, acc);
                acc = fmaf(w4.y, h4.y, acc);
                acc = fmaf(w4.z, h4.z, acc);
                acc = fmaf(w4.w, h4.w, acc);
            }
            ts[tok][j] = acc + b_out[j];
        }
    }
    __syncthreads();

    // warp w: log_softmax for token w (lanes cover j and j+32)
    const int wrp  = tid >> 5;
    const int lane = tid & 31;
    if (wrp < OB_TOK) {
        const float v0 = (lane      < T_TAGS) ? ts[wrp][lane]      : -1e30f;
        const float v1 = (lane + 32 < T_TAGS) ? ts[wrp][lane + 32] : -1e30f;
        float mx = fmaxf(v0, v1);
#pragma unroll
        for (int off = 16; off; off >>= 1)
            mx = fmaxf(mx, __shfl_xor_sync(0xffffffffu, mx, off));
        float sum = ((lane      < T_TAGS) ? expf(v0 - mx) : 0.f)
                  + ((lane + 32 < T_TAGS) ? expf(v1 - mx) : 0.f);
#pragma unroll
        for (int off = 16; off; off >>= 1)
            sum += __shfl_xor_sync(0xffffffffu, sum, off);
        const float lse = mx + logf(sum);
        float* o = out + (size_t)(s0 + wrp) * T_TAGS;
        if (lane      < T_TAGS) o[lane]      = v0 - lse;
        if (lane + 32 < T_TAGS) o[lane + 32] = v1 - lse;
    }
}

// ---------------- launch ----------------
extern "C" void kernel_launch(void* const* d_in, const int* in_sizes, int n_in,
                              void* d_out, int out_size)
{
    const int*   sent  = (const int*)  d_in[0];
    const float* emb   = (const float*)d_in[1];
    const float* W_ih  = (const float*)d_in[2];
    const float* W_hh  = (const float*)d_in[3];
    const float* b_ih  = (const float*)d_in[4];
    const float* b_hh  = (const float*)d_in[5];
    const float* W_out = (const float*)d_in[6];
    const float* b_out = (const float*)d_in[7];
    const float* h0    = (const float*)d_in[8];
    float* out = (float*)d_out;

    (void)in_sizes; (void)n_in; (void)out_size;

    init_cnt_kernel<<<1, 256>>>();

    dim3 ggrid(H_DIM / GBN, S_LEN / GBM);
    xi_gemm_kernel<<<ggrid, 256>>>(sent, emb, W_ih, b_ih, b_hh);

    rnn_kernel<<<RB_NBLK, RB_THREADS>>>(W_hh, h0);

    head_kernel<<<S_LEN / OB_TOK, OB_THREADS>>>(W_out, b_out, out);
}

// round 10
// speedup vs baseline: 4.7811x; 1.1375x over previous
#include <cuda_runtime.h>
#include <math.h>
#include <stdint.h>

#define S_LEN   8192
#define E_DIM   1024
#define H_DIM   2048
#define T_TAGS  50

// ---------------- persistent recurrence config ----------------
#define RB_NBLK    128
#define RB_ROWS    16          // H rows per block (128*16 = 2048)
#define RB_THREADS 256         // 8 warps
#define N_GRP      8           // h chunks / counters (one per warp)
#define GRP_CTAS   (RB_NBLK / N_GRP)    // 16 producer CTAs per chunk
#define CHUNK      (H_DIM / N_GRP)      // 256 floats per chunk

// ---------------- scratch (static device memory; no allocs) ----------------
__device__ float g_xi[(size_t)S_LEN * H_DIM];    // 64 MB
__device__ float g_rnn[(size_t)S_LEN * H_DIM];   // 64 MB
__device__ unsigned g_cnt8[N_GRP * 32];          // 8 counters, 128B apart (R6-proven)

__global__ void init_cnt_kernel() {
    if (threadIdx.x < N_GRP * 32) g_cnt8[threadIdx.x] = 0u;
}

// ---------------- packed f32x2 helpers ----------------
__device__ __forceinline__ unsigned long long ffma2(unsigned long long a,
                                                    unsigned long long b,
                                                    unsigned long long c) {
    unsigned long long d;
    asm("fma.rn.f32x2 %0, %1, %2, %3;" : "=l"(d) : "l"(a), "l"(b), "l"(c));
    return d;
}
__device__ __forceinline__ unsigned long long addf2(unsigned long long a,
                                                    unsigned long long b) {
    unsigned long long d;
    asm("add.rn.f32x2 %0, %1, %2;" : "=l"(d) : "l"(a), "l"(b));
    return d;
}

// ---------------- Kernel 1: fused embedding gather + xi GEMM (R3-proven) ----
#define GBM 64
#define GBN 64
#define GBK 16

__global__ __launch_bounds__(256) void xi_gemm_kernel(
    const int*   __restrict__ sent,
    const float* __restrict__ emb,
    const float* __restrict__ W_ih,
    const float* __restrict__ b_ih,
    const float* __restrict__ b_hh)
{
    __shared__ float As[GBM][GBK + 1];
    __shared__ float Bs[GBK][GBN + 4];
    __shared__ int   sidx[GBM];

    const int tid = threadIdx.x;
    const int m0  = blockIdx.y * GBM;
    const int n0  = blockIdx.x * GBN;

    if (tid < GBM) sidx[tid] = sent[m0 + tid];
    __syncthreads();

    const int lr = tid >> 2;
    const int lk = (tid & 3) * 4;
    const int tx = tid & 15;
    const int ty = tid >> 4;

    float acc[4][4];
#pragma unroll
    for (int i = 0; i < 4; i++)
#pragma unroll
        for (int j = 0; j < 4; j++) acc[i][j] = 0.f;

    const float* arow = emb  + (size_t)sidx[lr] * E_DIM;
    const float* brow = W_ih + (size_t)(n0 + lr) * E_DIM;

    for (int kt = 0; kt < E_DIM; kt += GBK) {
        float4 av = *(const float4*)(arow + kt + lk);
        float4 bv = *(const float4*)(brow + kt + lk);
        As[lr][lk + 0] = av.x; As[lr][lk + 1] = av.y;
        As[lr][lk + 2] = av.z; As[lr][lk + 3] = av.w;
        Bs[lk + 0][lr] = bv.x; Bs[lk + 1][lr] = bv.y;
        Bs[lk + 2][lr] = bv.z; Bs[lk + 3][lr] = bv.w;
        __syncthreads();

#pragma unroll
        for (int k = 0; k < GBK; k++) {
            float a0 = As[ty * 4 + 0][k];
            float a1 = As[ty * 4 + 1][k];
            float a2 = As[ty * 4 + 2][k];
            float a3 = As[ty * 4 + 3][k];
            float4 b4 = *(const float4*)&Bs[k][tx * 4];
            acc[0][0] = fmaf(a0, b4.x, acc[0][0]);
            acc[0][1] = fmaf(a0, b4.y, acc[0][1]);
            acc[0][2] = fmaf(a0, b4.z, acc[0][2]);
            acc[0][3] = fmaf(a0, b4.w, acc[0][3]);
            acc[1][0] = fmaf(a1, b4.x, acc[1][0]);
            acc[1][1] = fmaf(a1, b4.y, acc[1][1]);
            acc[1][2] = fmaf(a1, b4.z, acc[1][2]);
            acc[1][3] = fmaf(a1, b4.w, acc[1][3]);
            acc[2][0] = fmaf(a2, b4.x, acc[2][0]);
            acc[2][1] = fmaf(a2, b4.y, acc[2][1]);
            acc[2][2] = fmaf(a2, b4.z, acc[2][2]);
            acc[2][3] = fmaf(a2, b4.w, acc[2][3]);
            acc[3][0] = fmaf(a3, b4.x, acc[3][0]);
            acc[3][1] = fmaf(a3, b4.y, acc[3][1]);
            acc[3][2] = fmaf(a3, b4.z, acc[3][2]);
            acc[3][3] = fmaf(a3, b4.w, acc[3][3]);
        }
        __syncthreads();
    }

#pragma unroll
    for (int j = 0; j < 4; j++) {
        const int h = n0 + tx * 4 + j;
        const float bias = b_ih[h] + b_hh[h];
#pragma unroll
        for (int i = 0; i < 4; i++) {
            const int s = m0 + ty * 4 + i;
            g_xi[(size_t)s * H_DIM + h] = acc[i][j] + bias;
        }
    }
}

// ---------------- Kernel 2: persistent Elman recurrence ----------------
// COLUMN-SPLIT register matvec: warp w owns h columns [256w, 256w+256);
// lane l holds W[16 rows][8 cols] in 64 f32x2 regs AND receives exactly its
// 8 h values from the post-acquire __ldcg (h never touches SMEM). Cross-lane
// reduce: f32x2 butterfly; cross-warp: 16 floats/warp via SMEM. Warp 0 sums,
// tanh, publishes all 16 rows as ONE coalesced 64B store, then releases the
// group counter. Sync semantics = R6 verbatim (bench-proven):
// red.release counter / ld.acquire poll / __ldcg data.
__global__ void __launch_bounds__(RB_THREADS, 1) rnn_kernel(
    const float* __restrict__ W_hh,
    const float* __restrict__ h0)
{
    __shared__ __align__(16) float part[N_GRP][16];  // per-warp row partials

    const int b    = blockIdx.x;
    const int tid  = threadIdx.x;
    const int warp = tid >> 5;
    const int lane = tid & 31;
    const int row0 = b * RB_ROWS;

    // ---- W registers: rows 0..15, cols warp*256 + lane*8 .. +7 ----
    unsigned long long W2[16][4];
    {
        const float* wb = W_hh + (size_t)row0 * H_DIM + warp * CHUNK + lane * 8;
#pragma unroll
        for (int r = 0; r < 16; r++) {
            ulonglong2 u = *(const ulonglong2*)(wb + (size_t)r * H_DIM);
            ulonglong2 v = *(const ulonglong2*)(wb + (size_t)r * H_DIM + 4);
            W2[r][0] = u.x; W2[r][1] = u.y; W2[r][2] = v.x; W2[r][3] = v.y;
        }
    }

    // ---- h registers init from h0 (this lane's 8 columns) ----
    unsigned long long h2[4];
    {
        const float* hp = h0 + warp * CHUNK + lane * 8;
        ulonglong2 u = *(const ulonglong2*)hp;
        ulonglong2 v = *(const ulonglong2*)(hp + 4);
        h2[0] = u.x; h2[1] = u.y; h2[2] = v.x; h2[3] = v.y;
    }

    // xi for this CTA's rows: warp 0, lanes 0..15 (one row each)
    float xi_cur = 0.f;
    if (warp == 0 && lane < 16) xi_cur = g_xi[row0 + lane];

    unsigned* my_cnt   = &g_cnt8[(b >> 4) * 32];   // this CTA's group counter
    unsigned* poll_cnt = &g_cnt8[warp * 32];       // counter of chunk `warp`

    const uint32_t part_addr =
        (uint32_t)__cvta_generic_to_shared(&part[warp][0]);

    for (int t = 0; t < S_LEN; t++) {
        // prefetch xi for t+1 (plain LDG, hidden under matvec+reduce)
        float xi_nxt = 0.f;
        if (warp == 0 && lane < 16 && t + 1 < S_LEN)
            xi_nxt = g_xi[(size_t)(t + 1) * H_DIM + row0 + lane];

        // ---- matvec: 16 rows x 8 cols per lane, all in registers ----
        unsigned long long acc[16];
#pragma unroll
        for (int r = 0; r < 16; r++) {
            acc[r] = ffma2(W2[r][0], h2[0], 0ull);
            acc[r] = ffma2(W2[r][1], h2[1], acc[r]);
            acc[r] = ffma2(W2[r][2], h2[2], acc[r]);
            acc[r] = ffma2(W2[r][3], h2[3], acc[r]);
        }
        // fold k-halves, pack row pairs: q[j] = {row 2j, row 2j+1}
        unsigned long long q[8];
#pragma unroll
        for (int j = 0; j < 8; j++) {
            float l0, u0, l1, u1;
            asm("mov.b64 {%0, %1}, %2;" : "=f"(l0), "=f"(u0) : "l"(acc[2 * j]));
            asm("mov.b64 {%0, %1}, %2;" : "=f"(l1), "=f"(u1) : "l"(acc[2 * j + 1]));
            const float s0 = l0 + u0;
            const float s1 = l1 + u1;
            asm("mov.b64 %0, {%1, %2};" : "=l"(q[j]) : "f"(s0), "f"(s1));
        }
        // ---- full butterfly across 32 lanes (every lane gets all 16 sums) --
#pragma unroll
        for (int off = 16; off; off >>= 1) {
#pragma unroll
            for (int j = 0; j < 8; j++) {
                unsigned lo = (unsigned)q[j];
                unsigned hi = (unsigned)(q[j] >> 32);
                lo = __shfl_xor_sync(0xffffffffu, lo, off);
                hi = __shfl_xor_sync(0xffffffffu, hi, off);
                q[j] = addf2(q[j], ((unsigned long long)hi << 32) | lo);
            }
        }
        // lane 0 writes this warp's 16 row-partials to SMEM (4x 16B stores)
        if (lane == 0) {
            asm volatile("st.shared.v2.u64 [%0], {%1, %2};"
                         :: "r"(part_addr), "l"(q[0]), "l"(q[1]) : "memory");
            asm volatile("st.shared.v2.u64 [%0], {%1, %2};"
                         :: "r"(part_addr + 16), "l"(q[2]), "l"(q[3]) : "memory");
            asm volatile("st.shared.v2.u64 [%0], {%1, %2};"
                         :: "r"(part_addr + 32), "l"(q[4]), "l"(q[5]) : "memory");
            asm volatile("st.shared.v2.u64 [%0], {%1, %2};"
                         :: "r"(part_addr + 48), "l"(q[6]), "l"(q[7]) : "memory");
        }
        __syncthreads();   // bar1: all partials visible

        // ---- warp 0: cross-warp sum, tanh, coalesced publish, release ----
        if (warp == 0) {
            if (lane < 16) {
                const float s =
                    ((part[0][lane] + part[1][lane]) +
                     (part[2][lane] + part[3][lane])) +
                    ((part[4][lane] + part[5][lane]) +
                     (part[6][lane] + part[7][lane]));
                const float hn = tanhf(s + xi_cur);
                __stcg(g_rnn + (size_t)t * H_DIM + row0 + lane, hn);
            }
            __syncwarp();   // warp0's 16 stores happen-before lane0's release
            if (lane == 0) {
                asm volatile("red.release.gpu.global.add.u32 [%0], %1;"
                             :: "l"(my_cnt), "r"(1u) : "memory");
            }
        }
        xi_cur = xi_nxt;

        if (t + 1 < S_LEN) {
            // acquire-poll chunk `warp`'s counter (R6-proven)
            const unsigned want = (unsigned)(GRP_CTAS * (t + 1));
            unsigned v;
            do {
                asm volatile("ld.acquire.gpu.global.u32 %0, [%1];"
                             : "=r"(v) : "l"(poll_cnt) : "memory");
            } while (v < want);

            // load this lane's 8 h values straight into registers (L1 bypass)
            const float* hp = g_rnn + (size_t)t * H_DIM + warp * CHUNK + lane * 8;
            uint4 A = __ldcg((const uint4*)hp);
            uint4 B = __ldcg((const uint4*)(hp + 4));
            h2[0] = ((unsigned long long)A.y << 32) | A.x;
            h2[1] = ((unsigned long long)A.w << 32) | A.z;
            h2[2] = ((unsigned long long)B.y << 32) | B.x;
            h2[3] = ((unsigned long long)B.w << 32) | B.z;

            __syncthreads();  // bar2: warp0 done with part[] before next write
        }
    }
}

// ---------------- Kernel 3: tag head + log_softmax (R5-proven) ----------------
#define OB_TOK     4
#define OB_THREADS 128

__global__ __launch_bounds__(OB_THREADS) void head_kernel(
    const float* __restrict__ W_out,
    const float* __restrict__ b_out,
    float*       __restrict__ out)
{
    __shared__ float shh[OB_TOK][H_DIM];
    __shared__ float ts[OB_TOK][T_TAGS];

    const int tid = threadIdx.x;
    const int s0  = blockIdx.x * OB_TOK;

    {
        const float4* src = (const float4*)(g_rnn + (size_t)s0 * H_DIM);
        float4*       dst = (float4*)&shh[0][0];
        for (int i = tid; i < OB_TOK * H_DIM / 4; i += OB_THREADS) dst[i] = src[i];
    }
    __syncthreads();

    if (tid < T_TAGS) {
        const float* w = W_out + (size_t)tid * H_DIM;
        float a0 = 0.f, a1 = 0.f, a2 = 0.f, a3 = 0.f;
        for (int c = 0; c < H_DIM; c += 4) {
            float4 w4 = *(const float4*)(w + c);
            float4 h0v = *(const float4*)&shh[0][c];
            float4 h1v = *(const float4*)&shh[1][c];
            float4 h2v = *(const float4*)&shh[2][c];
            float4 h3v = *(const float4*)&shh[3][c];
            a0 = fmaf(w4.x, h0v.x, a0); a0 = fmaf(w4.y, h0v.y, a0);
            a0 = fmaf(w4.z, h0v.z, a0); a0 = fmaf(w4.w, h0v.w, a0);
            a1 = fmaf(w4.x, h1v.x, a1); a1 = fmaf(w4.y, h1v.y, a1);
            a1 = fmaf(w4.z, h1v.z, a1); a1 = fmaf(w4.w, h1v.w, a1);
            a2 = fmaf(w4.x, h2v.x, a2); a2 = fmaf(w4.y, h2v.y, a2);
            a2 = fmaf(w4.z, h2v.z, a2); a2 = fmaf(w4.w, h2v.w, a2);
            a3 = fmaf(w4.x, h3v.x, a3); a3 = fmaf(w4.y, h3v.y, a3);
            a3 = fmaf(w4.z, h3v.z, a3); a3 = fmaf(w4.w, h3v.w, a3);
        }
        const float bo = b_out[tid];
        ts[0][tid] = a0 + bo;
        ts[1][tid] = a1 + bo;
        ts[2][tid] = a2 + bo;
        ts[3][tid] = a3 + bo;
    }
    __syncthreads();

    if (tid < OB_TOK) {
        float mx = -1e30f;
        for (int j = 0; j < T_TAGS; j++) mx = fmaxf(mx, ts[tid][j]);
        float sum = 0.f;
        for (int j = 0; j < T_TAGS; j++) sum += expf(ts[tid][j] - mx);
        const float lse = mx + logf(sum);
        float* o = out + (size_t)(s0 + tid) * T_TAGS;
        for (int j = 0; j < T_TAGS; j++) o[j] = ts[tid][j] - lse;
    }
}

// ---------------- launch ----------------
extern "C" void kernel_launch(void* const* d_in, const int* in_sizes, int n_in,
                              void* d_out, int out_size)
{
    const int*   sent  = (const int*)  d_in[0];
    const float* emb   = (const float*)d_in[1];
    const float* W_ih  = (const float*)d_in[2];
    const float* W_hh  = (const float*)d_in[3];
    const float* b_ih  = (const float*)d_in[4];
    const float* b_hh  = (const float*)d_in[5];
    const float* W_out = (const float*)d_in[6];
    const float* b_out = (const float*)d_in[7];
    const float* h0    = (const float*)d_in[8];
    float* out = (float*)d_out;

    (void)in_sizes; (void)n_in; (void)out_size;

    init_cnt_kernel<<<1, 256>>>();

    dim3 ggrid(H_DIM / GBN, S_LEN / GBM);
    xi_gemm_kernel<<<ggrid, 256>>>(sent, emb, W_ih, b_ih, b_hh);

    rnn_kernel<<<RB_NBLK, RB_THREADS>>>(W_hh, h0);

    head_kernel<<<S_LEN / OB_TOK, OB_THREADS>>>(W_out, b_out, out);
}

// round 11
// speedup vs baseline: 4.9193x; 1.0289x over previous
#include <cuda_runtime.h>
#include <math.h>
#include <stdint.h>

#define S_LEN   8192
#define E_DIM   1024
#define H_DIM   2048
#define T_TAGS  50

// ---------------- persistent recurrence config ----------------
#define RB_NBLK    128
#define RB_ROWS    16          // H rows per block (128*16 = 2048)
#define RB_THREADS 256         // 8 warps
#define N_GRP      8           // h chunks / counters (one per warp)
#define GRP_CTAS   (RB_NBLK / N_GRP)    // 16 producer CTAs per chunk
#define CHUNK      (H_DIM / N_GRP)      // 256 floats per chunk

// ---------------- scratch (static device memory; no allocs) ----------------
__device__ float g_xi[(size_t)S_LEN * H_DIM];    // 64 MB
__device__ float g_rnn[(size_t)S_LEN * H_DIM];   // 64 MB
__device__ unsigned g_cnt8[N_GRP * 32];          // 8 counters, 128B apart

__global__ void init_cnt_kernel() {
    if (threadIdx.x < N_GRP * 32) g_cnt8[threadIdx.x] = 0u;
}

// ---------------- packed f32x2 helpers ----------------
__device__ __forceinline__ unsigned long long ffma2(unsigned long long a,
                                                    unsigned long long b,
                                                    unsigned long long c) {
    unsigned long long d;
    asm("fma.rn.f32x2 %0, %1, %2, %3;" : "=l"(d) : "l"(a), "l"(b), "l"(c));
    return d;
}
__device__ __forceinline__ unsigned long long addf2(unsigned long long a,
                                                    unsigned long long b) {
    unsigned long long d;
    asm("add.rn.f32x2 %0, %1, %2;" : "=l"(d) : "l"(a), "l"(b));
    return d;
}
// 64-bit shfl.xor via two 32-bit shfls
__device__ __forceinline__ unsigned long long shflx2(unsigned long long v,
                                                     int mask) {
    unsigned lo = (unsigned)v, hi = (unsigned)(v >> 32);
    lo = __shfl_xor_sync(0xffffffffu, lo, mask);
    hi = __shfl_xor_sync(0xffffffffu, hi, mask);
    return ((unsigned long long)hi << 32) | lo;
}

// fast tanh: 1 - 2/(e^{2x}+1); inf-safe, ~1e-6 rel err (budget is 1e-3)
__device__ __forceinline__ float tanh_fast(float x) {
    const float e2 = __expf(2.f * x);
    return 1.f - __fdividef(2.f, e2 + 1.f);
}

// ---------------- Kernel 1: fused embedding gather + xi GEMM (R3-proven) ----
#define GBM 64
#define GBN 64
#define GBK 16

__global__ __launch_bounds__(256) void xi_gemm_kernel(
    const int*   __restrict__ sent,
    const float* __restrict__ emb,
    const float* __restrict__ W_ih,
    const float* __restrict__ b_ih,
    const float* __restrict__ b_hh)
{
    __shared__ float As[GBM][GBK + 1];
    __shared__ float Bs[GBK][GBN + 4];
    __shared__ int   sidx[GBM];

    const int tid = threadIdx.x;
    const int m0  = blockIdx.y * GBM;
    const int n0  = blockIdx.x * GBN;

    if (tid < GBM) sidx[tid] = sent[m0 + tid];
    __syncthreads();

    const int lr = tid >> 2;
    const int lk = (tid & 3) * 4;
    const int tx = tid & 15;
    const int ty = tid >> 4;

    float acc[4][4];
#pragma unroll
    for (int i = 0; i < 4; i++)
#pragma unroll
        for (int j = 0; j < 4; j++) acc[i][j] = 0.f;

    const float* arow = emb  + (size_t)sidx[lr] * E_DIM;
    const float* brow = W_ih + (size_t)(n0 + lr) * E_DIM;

    for (int kt = 0; kt < E_DIM; kt += GBK) {
        float4 av = *(const float4*)(arow + kt + lk);
        float4 bv = *(const float4*)(brow + kt + lk);
        As[lr][lk + 0] = av.x; As[lr][lk + 1] = av.y;
        As[lr][lk + 2] = av.z; As[lr][lk + 3] = av.w;
        Bs[lk + 0][lr] = bv.x; Bs[lk + 1][lr] = bv.y;
        Bs[lk + 2][lr] = bv.z; Bs[lk + 3][lr] = bv.w;
        __syncthreads();

#pragma unroll
        for (int k = 0; k < GBK; k++) {
            float a0 = As[ty * 4 + 0][k];
            float a1 = As[ty * 4 + 1][k];
            float a2 = As[ty * 4 + 2][k];
            float a3 = As[ty * 4 + 3][k];
            float4 b4 = *(const float4*)&Bs[k][tx * 4];
            acc[0][0] = fmaf(a0, b4.x, acc[0][0]);
            acc[0][1] = fmaf(a0, b4.y, acc[0][1]);
            acc[0][2] = fmaf(a0, b4.z, acc[0][2]);
            acc[0][3] = fmaf(a0, b4.w, acc[0][3]);
            acc[1][0] = fmaf(a1, b4.x, acc[1][0]);
            acc[1][1] = fmaf(a1, b4.y, acc[1][1]);
            acc[1][2] = fmaf(a1, b4.z, acc[1][2]);
            acc[1][3] = fmaf(a1, b4.w, acc[1][3]);
            acc[2][0] = fmaf(a2, b4.x, acc[2][0]);
            acc[2][1] = fmaf(a2, b4.y, acc[2][1]);
            acc[2][2] = fmaf(a2, b4.z, acc[2][2]);
            acc[2][3] = fmaf(a2, b4.w, acc[2][3]);
            acc[3][0] = fmaf(a3, b4.x, acc[3][0]);
            acc[3][1] = fmaf(a3, b4.y, acc[3][1]);
            acc[3][2] = fmaf(a3, b4.z, acc[3][2]);
            acc[3][3] = fmaf(a3, b4.w, acc[3][3]);
        }
        __syncthreads();
    }

#pragma unroll
    for (int j = 0; j < 4; j++) {
        const int h = n0 + tx * 4 + j;
        const float bias = b_ih[h] + b_hh[h];
#pragma unroll
        for (int i = 0; i < 4; i++) {
            const int s = m0 + ty * 4 + i;
            g_xi[(size_t)s * H_DIM + h] = acc[i][j] + bias;
        }
    }
}

// ---------------- Kernel 2: persistent Elman recurrence ----------------
// Column-split register matvec (R10-proven). New in R11:
//  - halving-payload warp reduction (9 shfls instead of 80)
//  - part[] double-buffered by t&1 -> bar2 removed (one barrier per step)
//  - fast tanh on the publish critical path
// Sync semantics unchanged (R6/R10-proven): red.release counters,
// ld.acquire poll, __ldcg data.
__global__ void __launch_bounds__(RB_THREADS, 1) rnn_kernel(
    const float* __restrict__ W_hh,
    const float* __restrict__ h0)
{
    __shared__ __align__(16) float part[2][N_GRP][16];  // double-buffered

    const int b    = blockIdx.x;
    const int tid  = threadIdx.x;
    const int warp = tid >> 5;
    const int lane = tid & 31;
    const int row0 = b * RB_ROWS;

    // ---- W registers: rows 0..15, cols warp*256 + lane*8 .. +7 ----
    unsigned long long W2[16][4];
    {
        const float* wb = W_hh + (size_t)row0 * H_DIM + warp * CHUNK + lane * 8;
#pragma unroll
        for (int r = 0; r < 16; r++) {
            ulonglong2 u = *(const ulonglong2*)(wb + (size_t)r * H_DIM);
            ulonglong2 v = *(const ulonglong2*)(wb + (size_t)r * H_DIM + 4);
            W2[r][0] = u.x; W2[r][1] = u.y; W2[r][2] = v.x; W2[r][3] = v.y;
        }
    }

    // ---- h registers init from h0 (this lane's 8 columns) ----
    unsigned long long h2[4];
    {
        const float* hp = h0 + warp * CHUNK + lane * 8;
        ulonglong2 u = *(const ulonglong2*)hp;
        ulonglong2 v = *(const ulonglong2*)(hp + 4);
        h2[0] = u.x; h2[1] = u.y; h2[2] = v.x; h2[3] = v.y;
    }

    // xi for this CTA's rows: warp 0, lanes 0..15 (one row each)
    float xi_cur = 0.f;
    if (warp == 0 && lane < 16) xi_cur = g_xi[row0 + lane];

    unsigned* my_cnt   = &g_cnt8[(b >> 4) * 32];   // this CTA's group counter
    unsigned* poll_cnt = &g_cnt8[warp * 32];       // counter of chunk `warp`

    const bool b4 = (lane & 16) != 0;
    const bool b3 = (lane & 8)  != 0;
    const bool b2 = (lane & 4)  != 0;
    const bool b1 = (lane & 2)  != 0;

    for (int t = 0; t < S_LEN; t++) {
        const int buf = t & 1;

        // prefetch xi for t+1 (hidden under matvec+reduce)
        float xi_nxt = 0.f;
        if (warp == 0 && lane < 16 && t + 1 < S_LEN)
            xi_nxt = g_xi[(size_t)(t + 1) * H_DIM + row0 + lane];

        // ---- matvec: 16 rows x 8 cols per lane, all in registers ----
        unsigned long long acc[16];
#pragma unroll
        for (int r = 0; r < 16; r++) {
            acc[r] = ffma2(W2[r][0], h2[0], 0ull);
            acc[r] = ffma2(W2[r][1], h2[1], acc[r]);
            acc[r] = ffma2(W2[r][2], h2[2], acc[r]);
            acc[r] = ffma2(W2[r][3], h2[3], acc[r]);
        }
        // fold k-halves, pack row pairs: q[j] = {row 2j, row 2j+1}
        unsigned long long q[8];
#pragma unroll
        for (int j = 0; j < 8; j++) {
            float l0, u0, l1, u1;
            asm("mov.b64 {%0, %1}, %2;" : "=f"(l0), "=f"(u0) : "l"(acc[2 * j]));
            asm("mov.b64 {%0, %1}, %2;" : "=f"(l1), "=f"(u1) : "l"(acc[2 * j + 1]));
            const float s0 = l0 + u0;
            const float s1 = l1 + u1;
            asm("mov.b64 %0, {%1, %2};" : "=l"(q[j]) : "f"(s0), "f"(s1));
        }

        // ---- halving-payload reduction: 9 shfls total ----
        // round 1 (xor16): payload 8 -> 4; lo lanes keep rows 0..7, hi 8..15
        unsigned long long n[4];
#pragma unroll
        for (int j = 0; j < 4; j++) {
            const unsigned long long keep = b4 ? q[j + 4] : q[j];
            const unsigned long long send = b4 ? q[j]     : q[j + 4];
            n[j] = addf2(keep, shflx2(send, 16));
        }
        // round 2 (xor8): payload 4 -> 2
        unsigned long long m[2];
#pragma unroll
        for (int j = 0; j < 2; j++) {
            const unsigned long long keep = b3 ? n[j + 2] : n[j];
            const unsigned long long send = b3 ? n[j]     : n[j + 2];
            m[j] = addf2(keep, shflx2(send, 8));
        }
        // round 3 (xor4): payload 2 -> 1 (rows {R, R+1})
        unsigned long long p;
        {
            const unsigned long long keep = b2 ? m[1] : m[0];
            const unsigned long long send = b2 ? m[0] : m[1];
            p = addf2(keep, shflx2(send, 4));
        }
        // round 4 (xor2): split pair -> one scalar row
        float val;
        {
            float e, f;
            asm("mov.b64 {%0, %1}, %2;" : "=f"(e), "=f"(f) : "l"(p));
            const float keep = b1 ? f : e;
            const float send = b1 ? e : f;
            val = keep + __shfl_xor_sync(0xffffffffu, send, 2);
        }
        // round 5 (xor1): fold last column halves
        val += __shfl_xor_sync(0xffffffffu, val, 1);
        // lane 2*r (and 2*r+1) now hold row r's full partial for this chunk
        if ((lane & 1) == 0) part[buf][warp][lane >> 1] = val;

        __syncthreads();   // bar1: all partials of step t visible

        // ---- warp 0: cross-warp sum, tanh, coalesced publish, release ----
        if (warp == 0) {
            if (lane < 16) {
                const float s =
                    ((part[buf][0][lane] + part[buf][1][lane]) +
                     (part[buf][2][lane] + part[buf][3][lane])) +
                    ((part[buf][4][lane] + part[buf][5][lane]) +
                     (part[buf][6][lane] + part[buf][7][lane]));
                const float hn = tanh_fast(s + xi_cur);
                __stcg(g_rnn + (size_t)t * H_DIM + row0 + lane, hn);
            }
            __syncwarp();   // warp0's 16 stores happen-before lane0's release
            if (lane == 0) {
                asm volatile("red.release.gpu.global.add.u32 [%0], %1;"
                             :: "l"(my_cnt), "r"(1u) : "memory");
            }
        }
        xi_cur = xi_nxt;

        if (t + 1 < S_LEN) {
            // acquire-poll chunk `warp`'s counter (R6-proven)
            const unsigned want = (unsigned)(GRP_CTAS * (t + 1));
            unsigned v;
            do {
                asm volatile("ld.acquire.gpu.global.u32 %0, [%1];"
                             : "=r"(v) : "l"(poll_cnt) : "memory");
            } while (v < want);

            // load this lane's 8 h values straight into registers (L1 bypass)
            const float* hp = g_rnn + (size_t)t * H_DIM + warp * CHUNK + lane * 8;
            uint4 A = __ldcg((const uint4*)hp);
            uint4 B = __ldcg((const uint4*)(hp + 4));
            h2[0] = ((unsigned long long)A.y << 32) | A.x;
            h2[1] = ((unsigned long long)A.w << 32) | A.z;
            h2[2] = ((unsigned long long)B.y << 32) | B.x;
            h2[3] = ((unsigned long long)B.w << 32) | B.z;
            // no bar2: next step writes part[(t+1)&1]; warp0's reads of
            // part[t&1] complete before bar1(t+1), which precedes any
            // step-(t+2) overwrite of this buffer.
        }
    }
}

// ---------------- Kernel 3: tag head + log_softmax (R5-proven) ----------------
#define OB_TOK     4
#define OB_THREADS 128

__global__ __launch_bounds__(OB_THREADS) void head_kernel(
    const float* __restrict__ W_out,
    const float* __restrict__ b_out,
    float*       __restrict__ out)
{
    __shared__ float shh[OB_TOK][H_DIM];
    __shared__ float ts[OB_TOK][T_TAGS];

    const int tid = threadIdx.x;
    const int s0  = blockIdx.x * OB_TOK;

    {
        const float4* src = (const float4*)(g_rnn + (size_t)s0 * H_DIM);
        float4*       dst = (float4*)&shh[0][0];
        for (int i = tid; i < OB_TOK * H_DIM / 4; i += OB_THREADS) dst[i] = src[i];
    }
    __syncthreads();

    if (tid < T_TAGS) {
        const float* w = W_out + (size_t)tid * H_DIM;
        float a0 = 0.f, a1 = 0.f, a2 = 0.f, a3 = 0.f;
        for (int c = 0; c < H_DIM; c += 4) {
            float4 w4 = *(const float4*)(w + c);
            float4 h0v = *(const float4*)&shh[0][c];
            float4 h1v = *(const float4*)&shh[1][c];
            float4 h2v = *(const float4*)&shh[2][c];
            float4 h3v = *(const float4*)&shh[3][c];
            a0 = fmaf(w4.x, h0v.x, a0); a0 = fmaf(w4.y, h0v.y, a0);
            a0 = fmaf(w4.z, h0v.z, a0); a0 = fmaf(w4.w, h0v.w, a0);
            a1 = fmaf(w4.x, h1v.x, a1); a1 = fmaf(w4.y, h1v.y, a1);
            a1 = fmaf(w4.z, h1v.z, a1); a1 = fmaf(w4.w, h1v.w, a1);
            a2 = fmaf(w4.x, h2v.x, a2); a2 = fmaf(w4.y, h2v.y, a2);
            a2 = fmaf(w4.z, h2v.z, a2); a2 = fmaf(w4.w, h2v.w, a2);
            a3 = fmaf(w4.x, h3v.x, a3); a3 = fmaf(w4.y, h3v.y, a3);
            a3 = fmaf(w4.z, h3v.z, a3); a3 = fmaf(w4.w, h3v.w, a3);
        }
        const float bo = b_out[tid];
        ts[0][tid] = a0 + bo;
        ts[1][tid] = a1 + bo;
        ts[2][tid] = a2 + bo;
        ts[3][tid] = a3 + bo;
    }
    __syncthreads();

    if (tid < OB_TOK) {
        float mx = -1e30f;
        for (int j = 0; j < T_TAGS; j++) mx = fmaxf(mx, ts[tid][j]);
        float sum = 0.f;
        for (int j = 0; j < T_TAGS; j++) sum += expf(ts[tid][j] - mx);
        const float lse = mx + logf(sum);
        float* o = out + (size_t)(s0 + tid) * T_TAGS;
        for (int j = 0; j < T_TAGS; j++) o[j] = ts[tid][j] - lse;
    }
}

// ---------------- launch ----------------
extern "C" void kernel_launch(void* const* d_in, const int* in_sizes, int n_in,
                              void* d_out, int out_size)
{
    const int*   sent  = (const int*)  d_in[0];
    const float* emb   = (const float*)d_in[1];
    const float* W_ih  = (const float*)d_in[2];
    const float* W_hh  = (const float*)d_in[3];
    const float* b_ih  = (const float*)d_in[4];
    const float* b_hh  = (const float*)d_in[5];
    const float* W_out = (const float*)d_in[6];
    const float* b_out = (const float*)d_in[7];
    const float* h0    = (const float*)d_in[8];
    float* out = (float*)d_out;

    (void)in_sizes; (void)n_in; (void)out_size;

    init_cnt_kernel<<<1, 256>>>();

    dim3 ggrid(H_DIM / GBN, S_LEN / GBM);
    xi_gemm_kernel<<<ggrid, 256>>>(sent, emb, W_ih, b_ih, b_hh);

    rnn_kernel<<<RB_NBLK, RB_THREADS>>>(W_hh, h0);

    head_kernel<<<S_LEN / OB_TOK, OB_THREADS>>>(W_out, b_out, out);
}